// round 1
// baseline (speedup 1.0000x reference)
#include <cuda_runtime.h>
#include <math.h>

#define BB   2048
#define INN  512
#define HH   512
#define KFR  32
#define OUTN 512
#define KD   (INN + 2*HH)   // 1536
#define KC   (INN + HH)     // 1024
#define BH   (BB*HH)        // 1048576

// scratch (static device allocations are allowed)
__device__ float g_combined[BB * KD];       // [B, IN+H+H] = combined_d
__device__ float g_z[4][BB * HH];           // pre-activations: 0=i, 1=o, 2=c, 3=f

// ---------------------------------------------------------------------------
// concat: g_combined[b] = [sample[b], hidden[b], d_0[b]]
// ---------------------------------------------------------------------------
__global__ void concat_kernel(const float* __restrict__ sample,
                              const float* __restrict__ hidden,
                              const float* __restrict__ d0) {
    int idx = blockIdx.x * blockDim.x + threadIdx.x;   // over B*KD/4
    const int total = BB * KD / 4;
    if (idx >= total) return;
    int b  = idx / (KD / 4);
    int c4 = idx % (KD / 4);
    float4 v;
    if (c4 < INN / 4)            v = ((const float4*)sample)[b * (INN/4) + c4];
    else if (c4 < (INN+HH) / 4)  v = ((const float4*)hidden)[b * (HH/4) + (c4 - INN/4)];
    else                         v = ((const float4*)d0)[b * (HH/4) + (c4 - (INN+HH)/4)];
    ((float4*)g_combined)[idx] = v;
}

// ---------------------------------------------------------------------------
// 128x128x8 fp32 GEMM tile: C[m,n] = sum_k A[m,k]*W[n,k] + bias[n]
// A row-major [M, lda], W row-major [N, ldw] (K contiguous in both) -> NT gemm
// 256 threads, 8x8 per-thread microtile.
// ---------------------------------------------------------------------------
__device__ __forceinline__ void sgemm128(const float* __restrict__ A, int lda,
                                         const float* __restrict__ W, int ldw,
                                         const float* __restrict__ bias,
                                         float* __restrict__ C, int ldc,
                                         int K, int blockM, int blockN) {
    __shared__ float As[8][132];
    __shared__ float Ws[8][132];

    const int tid  = threadIdx.x;          // 0..255
    const int tx   = tid & 15;             // 0..15
    const int ty   = tid >> 4;             // 0..15
    const int lrow = tid >> 1;             // 0..127
    const int lc4  = (tid & 1) * 4;        // 0 or 4

    const float* Aptr = A + (size_t)(blockM + lrow) * lda + lc4;
    const float* Wptr = W + (size_t)(blockN + lrow) * ldw + lc4;

    float acc[8][8];
#pragma unroll
    for (int i = 0; i < 8; i++)
#pragma unroll
        for (int j = 0; j < 8; j++) acc[i][j] = 0.0f;

    for (int k0 = 0; k0 < K; k0 += 8) {
        float4 av = *(const float4*)(Aptr + k0);
        float4 wv = *(const float4*)(Wptr + k0);
        As[lc4 + 0][lrow] = av.x;  As[lc4 + 1][lrow] = av.y;
        As[lc4 + 2][lrow] = av.z;  As[lc4 + 3][lrow] = av.w;
        Ws[lc4 + 0][lrow] = wv.x;  Ws[lc4 + 1][lrow] = wv.y;
        Ws[lc4 + 2][lrow] = wv.z;  Ws[lc4 + 3][lrow] = wv.w;
        __syncthreads();

#pragma unroll
        for (int kk = 0; kk < 8; kk++) {
            float4 a0 = *(const float4*)&As[kk][ty * 8];
            float4 a1 = *(const float4*)&As[kk][ty * 8 + 4];
            float4 b0 = *(const float4*)&Ws[kk][tx * 8];
            float4 b1 = *(const float4*)&Ws[kk][tx * 8 + 4];
            float a[8] = {a0.x, a0.y, a0.z, a0.w, a1.x, a1.y, a1.z, a1.w};
            float b[8] = {b0.x, b0.y, b0.z, b0.w, b1.x, b1.y, b1.z, b1.w};
#pragma unroll
            for (int i = 0; i < 8; i++)
#pragma unroll
                for (int j = 0; j < 8; j++) acc[i][j] = fmaf(a[i], b[j], acc[i][j]);
        }
        __syncthreads();
    }

    // epilogue with bias, float4 stores
#pragma unroll
    for (int i = 0; i < 8; i++) {
        int row = blockM + ty * 8 + i;
        float* crow = C + (size_t)row * ldc + blockN + tx * 8;
        const float* brow = bias + blockN + tx * 8;
        float4 v0, v1;
        v0.x = acc[i][0] + brow[0]; v0.y = acc[i][1] + brow[1];
        v0.z = acc[i][2] + brow[2]; v0.w = acc[i][3] + brow[3];
        v1.x = acc[i][4] + brow[4]; v1.y = acc[i][5] + brow[5];
        v1.z = acc[i][6] + brow[6]; v1.w = acc[i][7] + brow[7];
        ((float4*)crow)[0] = v0;
        ((float4*)crow)[1] = v1;
    }
}

// all 4 gate GEMMs in one launch: blockIdx.z selects gate
__global__ __launch_bounds__(256, 2)
void gates_gemm_kernel(const float* __restrict__ Wi, const float* __restrict__ bi,
                       const float* __restrict__ Wo, const float* __restrict__ bo,
                       const float* __restrict__ Wc, const float* __restrict__ bc,
                       const float* __restrict__ Wf, const float* __restrict__ bf) {
    int z = blockIdx.z;
    const float* W; const float* bias; int K;
    if      (z == 0) { W = Wi; bias = bi; K = KC; }
    else if (z == 1) { W = Wo; bias = bo; K = KC; }
    else if (z == 2) { W = Wc; bias = bc; K = KC; }
    else             { W = Wf; bias = bf; K = KD; }
    sgemm128(g_combined, KD, W, K, bias, g_z[z], HH, K,
             blockIdx.y * 128, blockIdx.x * 128);
}

__global__ __launch_bounds__(256, 2)
void out_gemm_kernel(const float* __restrict__ hidden_new,
                     const float* __restrict__ Wout,
                     const float* __restrict__ bout,
                     float* __restrict__ out) {
    sgemm128(hidden_new, HH, Wout, HH, bout, out, OUTN, HH,
             blockIdx.y * 128, blockIdx.x * 128);
}

// ---------------------------------------------------------------------------
// fused elementwise: d_values, fractional-weight reduction, h_c_1 shift-copy,
// cell, hidden_new. One coalesced pass over cell_tensor, float4.
// ---------------------------------------------------------------------------
__device__ __forceinline__ float sigf(float x) { return 1.0f / (1.0f + expf(-x)); }

__global__ void fused_cell_kernel(const float* __restrict__ cell_t,
                                  float* __restrict__ dout) {
    int idx = blockIdx.x * blockDim.x + threadIdx.x;   // over BH/4
    const int nb4 = BH / 4;
    if (idx >= nb4) return;

    const float4* c4  = (const float4*)cell_t;
    float4* hid = (float4*)(dout + (size_t)BB * OUTN);
    float4* hc  = (float4*)(dout + (size_t)2 * BB * OUTN);
    float4* dv  = (float4*)(dout + (size_t)2 * BB * OUTN + (size_t)KFR * BH);

    float4 zf = ((const float4*)g_z[3])[idx];
    float4 d;
    d.x = 0.5f * sigf(zf.x); d.y = 0.5f * sigf(zf.y);
    d.z = 0.5f * sigf(zf.z); d.w = 0.5f * sigf(zf.w);
    dv[idx] = d;

    float4 w   = make_float4(1.f, 1.f, 1.f, 1.f);
    float4 acc = make_float4(0.f, 0.f, 0.f, 0.f);
#pragma unroll
    for (int j = KFR - 1; j >= 0; j--) {
        float fi  = (float)(KFR - 1 - j);       // i = 0..31 ascending
        float inv = 1.0f / (float)(KFR - j);    // 1/(i+1)
        w.x *= (fi - d.x) * inv;  w.y *= (fi - d.y) * inv;
        w.z *= (fi - d.z) * inv;  w.w *= (fi - d.w) * inv;
        float4 cv = c4[(size_t)j * nb4 + idx];
        acc.x = fmaf(w.x, cv.x, acc.x);  acc.y = fmaf(w.y, cv.y, acc.y);
        acc.z = fmaf(w.z, cv.z, acc.z);  acc.w = fmaf(w.w, cv.w, acc.w);
        if (j >= 1) hc[(size_t)(j - 1) * nb4 + idx] = cv;   // h_c_1 shift-copy
    }

    float4 zi = ((const float4*)g_z[0])[idx];
    float4 zo = ((const float4*)g_z[1])[idx];
    float4 zc = ((const float4*)g_z[2])[idx];

    float4 cell;
    cell.x = -acc.x + tanhf(zc.x) * sigf(zi.x);
    cell.y = -acc.y + tanhf(zc.y) * sigf(zi.y);
    cell.z = -acc.z + tanhf(zc.z) * sigf(zi.z);
    cell.w = -acc.w + tanhf(zc.w) * sigf(zi.w);
    hc[(size_t)(KFR - 1) * nb4 + idx] = cell;

    float4 hn;
    hn.x = tanhf(cell.x) * sigf(zo.x);
    hn.y = tanhf(cell.y) * sigf(zo.y);
    hn.z = tanhf(cell.z) * sigf(zo.z);
    hn.w = tanhf(cell.w) * sigf(zo.w);
    hid[idx] = hn;
}

// ---------------------------------------------------------------------------
extern "C" void kernel_launch(void* const* d_in, const int* in_sizes, int n_in,
                              void* d_out_v, int out_size) {
    const float* sample = (const float*)d_in[0];
    const float* hidden = (const float*)d_in[1];
    const float* cell_t = (const float*)d_in[2];
    const float* d0     = (const float*)d_in[3];
    const float* Wc     = (const float*)d_in[4];
    const float* bc     = (const float*)d_in[5];
    const float* Wi     = (const float*)d_in[6];
    const float* bi     = (const float*)d_in[7];
    const float* Wf     = (const float*)d_in[8];
    const float* bf     = (const float*)d_in[9];
    const float* Wo     = (const float*)d_in[10];
    const float* bo     = (const float*)d_in[11];
    const float* Wout   = (const float*)d_in[12];
    const float* bout   = (const float*)d_in[13];
    float* out = (float*)d_out_v;

    // 1) build combined_d = [sample | hidden | d_0]
    concat_kernel<<<(BB * KD / 4 + 255) / 256, 256>>>(sample, hidden, d0);

    // 2) all 4 gate GEMMs (i, o, c over K=1024; f over K=1536) in one launch
    dim3 ggrid(HH / 128, BB / 128, 4);
    gates_gemm_kernel<<<ggrid, 256>>>(Wi, bi, Wo, bo, Wc, bc, Wf, bf);

    // 3) fused elementwise: d_values, frac-weight reduction, h_c_1, cell, hidden_new
    fused_cell_kernel<<<(BH / 4 + 255) / 256, 256>>>(cell_t, out);

    // 4) output GEMM: hidden_new @ Wout^T + bout (reads hidden_new from d_out)
    dim3 ogrid(OUTN / 128, BB / 128, 1);
    out_gemm_kernel<<<ogrid, 256>>>(out + (size_t)BB * OUTN, Wout, bout, out);
}

// round 3
// speedup vs baseline: 2.5920x; 2.5920x over previous
#include <cuda_runtime.h>
#include <cuda_bf16.h>
#include <math.h>
#include <stdint.h>

#define BB   2048
#define INN  512
#define HH   512
#define KFR  32
#define OUTN 512
#define KD   1536            // IN + 2H (combined_d width)
#define KC   1024            // IN + H
#define BH   (BB*HH)

#define OFF_WI   0
#define OFF_WO   (512*1024)
#define OFF_WC   (2*512*1024)
#define OFF_WF   (3*512*1024)
#define OFF_WOUT (3*512*1024 + 512*1536)
#define W_TOTAL  (OFF_WOUT + 512*512)

#define TILE_B   16384       // one 128x64 bf16 tile in smem
#define STAGE_B  (4*TILE_B)  // Ahi, Alo, Bhi, Blo
#define SMEM_TOT (2*STAGE_B) // double buffered = 131072

// ---------------- static device scratch ----------------
__device__ __nv_bfloat16 g_comb_hi[BB*KD];
__device__ __nv_bfloat16 g_comb_lo[BB*KD];
__device__ __nv_bfloat16 g_w_hi[W_TOTAL];
__device__ __nv_bfloat16 g_w_lo[W_TOTAL];
__device__ __nv_bfloat16 g_hid_hi[BH];
__device__ __nv_bfloat16 g_hid_lo[BH];
__device__ float g_z[4][BH];          // pre-activations: 0=i, 1=o, 2=c, 3=f

// ---------------- PTX helpers (baseline ISA only; no sm_103a-gated instrs) ----
__device__ __forceinline__ uint32_t smem_u32(const void* p) {
    return (uint32_t)__cvta_generic_to_shared(p);
}

__device__ __forceinline__ void cp16(uint32_t daddr, const void* g) {
    asm volatile("cp.async.cg.shared.global [%0], [%1], 16;" :: "r"(daddr), "l"(g) : "memory");
}
#define CP_COMMIT() asm volatile("cp.async.commit_group;" ::: "memory")
template <int N>
__device__ __forceinline__ void cp_wait() {
    asm volatile("cp.async.wait_group %0;" :: "n"(N) : "memory");
}

__device__ __forceinline__ void ldsm4(uint32_t addr, uint32_t* r) {
    asm volatile("ldmatrix.sync.aligned.m8n8.x4.shared.b16 {%0,%1,%2,%3}, [%4];"
        : "=r"(r[0]), "=r"(r[1]), "=r"(r[2]), "=r"(r[3]) : "r"(addr));
}

__device__ __forceinline__ void mma_bf16(float* c, const uint32_t* a, const uint32_t* b) {
    asm volatile("mma.sync.aligned.m16n8k16.row.col.f32.bf16.bf16.f32 "
        "{%0,%1,%2,%3}, {%4,%5,%6,%7}, {%8,%9}, {%0,%1,%2,%3};"
        : "+f"(c[0]), "+f"(c[1]), "+f"(c[2]), "+f"(c[3])
        : "r"(a[0]), "r"(a[1]), "r"(a[2]), "r"(a[3]), "r"(b[0]), "r"(b[1]));
}

// ---------------------------------------------------------------------------
// cp.async loader: one K-chunk (64 cols) of the 4 tiles into one stage.
// 256 threads; per tile 128 rows x 8 x 16B chunks = 1024 cp16 -> 4 per thread.
// SW128-style swizzle: phys_col16 = col16 ^ (row & 7)
// ---------------------------------------------------------------------------
__device__ __forceinline__ void load_stage(uint32_t sbase,
    const char* a_hi, const char* a_lo, const char* b_hi, const char* b_lo,
    int lda_b, int ldb_b, int k0b, int tid) {
    const char* srcs[4] = {a_hi, a_lo, b_hi, b_lo};
    const int lds[4] = {lda_b, lda_b, ldb_b, ldb_b};
#pragma unroll
    for (int t = 0; t < 4; t++) {
#pragma unroll
        for (int i = 0; i < 4; i++) {
            int idx = i * 256 + tid;
            int row = idx >> 3;
            uint32_t ch = (uint32_t)(idx & 7) * 16;
            uint32_t off = (uint32_t)row * 128 + (ch ^ (((uint32_t)row & 7) << 4));
            cp16(sbase + t * TILE_B + off,
                 srcs[t] + (size_t)row * lds[t] + k0b + ch);
        }
    }
}

// ---------------------------------------------------------------------------
// split-bf16 mma.sync GEMM tile: C[m,n] = sum_k A[m,k]*B[n,k] + bias[n]
// A = Ahi+Alo, B = Bhi+Blo. 128x128 tile, 8 warps (4x2), warp tile 32x64.
// ---------------------------------------------------------------------------
__device__ __forceinline__ void mma_gemm_tile(
    const __nv_bfloat16* Ahi, const __nv_bfloat16* Alo, int lda,
    const __nv_bfloat16* Bhi, const __nv_bfloat16* Blo, int ldb,
    const float* __restrict__ bias, float* __restrict__ C, int ldc,
    int K, int blockM, int blockN) {
    extern __shared__ __align__(1024) char dsm[];
    const int tid  = threadIdx.x;
    const int lane = tid & 31;
    const int wid  = tid >> 5;
    const int wm   = wid & 3;    // 0..3 -> 32-row slab
    const int wn   = wid >> 2;   // 0..1 -> 64-col slab
    uint32_t sb = smem_u32(dsm);

    // per-lane ldmatrix address components
    const uint32_t a_kb = ((uint32_t)lane >> 4) * 16;          // 0/16
    const uint32_t b_kb = (((uint32_t)lane >> 3) & 1) * 16;    // 0/16
    uint32_t aRow[2], aXor[2];
#pragma unroll
    for (int mt = 0; mt < 2; mt++) {
        int r = wm * 32 + mt * 16 + (lane & 15);
        aRow[mt] = (uint32_t)r * 128;
        aXor[mt] = ((uint32_t)r & 7) << 4;
    }
    uint32_t bRow[4], bXor[4];
#pragma unroll
    for (int g = 0; g < 4; g++) {
        int r = wn * 64 + g * 16 + (((lane >> 4) << 3) + (lane & 7));
        bRow[g] = (uint32_t)r * 128;
        bXor[g] = ((uint32_t)r & 7) << 4;
    }

    float acc[2][8][4];
#pragma unroll
    for (int mt = 0; mt < 2; mt++)
#pragma unroll
        for (int nt = 0; nt < 8; nt++)
#pragma unroll
            for (int j = 0; j < 4; j++) acc[mt][nt][j] = 0.0f;

    const char* aH = (const char*)(Ahi + (size_t)blockM * lda);
    const char* aL = (const char*)(Alo + (size_t)blockM * lda);
    const char* bH = (const char*)(Bhi + (size_t)blockN * ldb);
    const char* bL = (const char*)(Blo + (size_t)blockN * ldb);
    const int lda_b = lda * 2, ldb_b = ldb * 2;
    const int NC = K / 64;

    load_stage(sb, aH, aL, bH, bL, lda_b, ldb_b, 0, tid);
    CP_COMMIT();

    for (int c = 0; c < NC; ++c) {
        const uint32_t st = sb + (uint32_t)(c & 1) * STAGE_B;
        if (c + 1 < NC) {
            load_stage(sb + (uint32_t)((c + 1) & 1) * STAGE_B,
                       aH, aL, bH, bL, lda_b, ldb_b, (c + 1) * 128, tid);
            CP_COMMIT();
            cp_wait<1>();
        } else {
            cp_wait<0>();
        }
        __syncthreads();

#pragma unroll
        for (int kk = 0; kk < 4; kk++) {
            uint32_t ah[2][4], al[2][4];
#pragma unroll
            for (int mt = 0; mt < 2; mt++) {
                uint32_t col = ((uint32_t)(kk * 32) + a_kb) ^ aXor[mt];
                ldsm4(st + 0 * TILE_B + aRow[mt] + col, ah[mt]);
                ldsm4(st + 1 * TILE_B + aRow[mt] + col, al[mt]);
            }
            uint32_t bh[8][2], bl[8][2];
#pragma unroll
            for (int g = 0; g < 4; g++) {
                uint32_t col = ((uint32_t)(kk * 32) + b_kb) ^ bXor[g];
                uint32_t r[4];
                ldsm4(st + 2 * TILE_B + bRow[g] + col, r);
                bh[2*g][0] = r[0]; bh[2*g][1] = r[1];
                bh[2*g+1][0] = r[2]; bh[2*g+1][1] = r[3];
                ldsm4(st + 3 * TILE_B + bRow[g] + col, r);
                bl[2*g][0] = r[0]; bl[2*g][1] = r[1];
                bl[2*g+1][0] = r[2]; bl[2*g+1][1] = r[3];
            }
#pragma unroll
            for (int mt = 0; mt < 2; mt++)
#pragma unroll
                for (int nt = 0; nt < 8; nt++) {
                    mma_bf16(acc[mt][nt], ah[mt], bh[nt]);
                    mma_bf16(acc[mt][nt], ah[mt], bl[nt]);
                    mma_bf16(acc[mt][nt], al[mt], bh[nt]);
                }
        }
        __syncthreads();
    }

    // epilogue: add bias, store fp32
#pragma unroll
    for (int mt = 0; mt < 2; mt++) {
        int r0 = blockM + wm * 32 + mt * 16 + (lane >> 2);
#pragma unroll
        for (int nt = 0; nt < 8; nt++) {
            int col = blockN + wn * 64 + nt * 8 + (lane & 3) * 2;
            float b0 = bias[col], b1 = bias[col + 1];
            float2 v0 = {acc[mt][nt][0] + b0, acc[mt][nt][1] + b1};
            float2 v1 = {acc[mt][nt][2] + b0, acc[mt][nt][3] + b1};
            *(float2*)(C + (size_t)r0 * ldc + col) = v0;
            *(float2*)(C + (size_t)(r0 + 8) * ldc + col) = v1;
        }
    }
}

// ---------------------------------------------------------------------------
__global__ __launch_bounds__(256, 1)
void gates_mma_kernel(const float* __restrict__ bi, const float* __restrict__ bo,
                      const float* __restrict__ bc, const float* __restrict__ bf) {
    int z = blockIdx.z;
    const __nv_bfloat16 *wh, *wl; const float* bias; int K;
    if      (z == 0) { wh = g_w_hi + OFF_WI; wl = g_w_lo + OFF_WI; bias = bi; K = KC; }
    else if (z == 1) { wh = g_w_hi + OFF_WO; wl = g_w_lo + OFF_WO; bias = bo; K = KC; }
    else if (z == 2) { wh = g_w_hi + OFF_WC; wl = g_w_lo + OFF_WC; bias = bc; K = KC; }
    else             { wh = g_w_hi + OFF_WF; wl = g_w_lo + OFF_WF; bias = bf; K = KD; }
    mma_gemm_tile(g_comb_hi, g_comb_lo, KD, wh, wl, K, bias, g_z[z], HH, K,
                  blockIdx.y * 128, blockIdx.x * 128);
}

__global__ __launch_bounds__(256, 1)
void out_mma_kernel(const float* __restrict__ bout, float* __restrict__ out) {
    mma_gemm_tile(g_hid_hi, g_hid_lo, HH,
                  g_w_hi + OFF_WOUT, g_w_lo + OFF_WOUT, HH,
                  bout, out, OUTN, HH, blockIdx.y * 128, blockIdx.x * 128);
}

// ---------------------------------------------------------------------------
// conversions: fp32 -> bf16 hi/lo split
// ---------------------------------------------------------------------------
__device__ __forceinline__ void split4(float4 v, __nv_bfloat16* hi, __nv_bfloat16* lo) {
    float f[4] = {v.x, v.y, v.z, v.w};
    union { __nv_bfloat16 h[4]; uint2 u; } H, L;
#pragma unroll
    for (int i = 0; i < 4; i++) {
        __nv_bfloat16 h = __float2bfloat16_rn(f[i]);
        H.h[i] = h;
        L.h[i] = __float2bfloat16_rn(f[i] - __bfloat162float(h));
    }
    *(uint2*)hi = H.u;
    *(uint2*)lo = L.u;
}

__global__ void comb_conv_kernel(const float* __restrict__ sample,
                                 const float* __restrict__ hidden,
                                 const float* __restrict__ d0) {
    int idx = blockIdx.x * blockDim.x + threadIdx.x;   // over BB*KD/4
    if (idx >= BB * KD / 4) return;
    int b  = idx / (KD / 4);
    int c4 = idx % (KD / 4);
    float4 v;
    if (c4 < INN / 4)            v = ((const float4*)sample)[b * (INN/4) + c4];
    else if (c4 < (INN+HH) / 4)  v = ((const float4*)hidden)[b * (HH/4) + (c4 - INN/4)];
    else                         v = ((const float4*)d0)[b * (HH/4) + (c4 - (INN+HH)/4)];
    split4(v, g_comb_hi + idx * 4, g_comb_lo + idx * 4);
}

__global__ void w_conv_kernel(const float* __restrict__ Wi, const float* __restrict__ Wo,
                              const float* __restrict__ Wc, const float* __restrict__ Wf,
                              const float* __restrict__ Wout) {
    int a = blockIdx.y;
    const float* src; size_t off; int n;
    if      (a == 0) { src = Wi;   off = OFF_WI;   n = 512 * 1024; }
    else if (a == 1) { src = Wo;   off = OFF_WO;   n = 512 * 1024; }
    else if (a == 2) { src = Wc;   off = OFF_WC;   n = 512 * 1024; }
    else if (a == 3) { src = Wf;   off = OFF_WF;   n = 512 * 1536; }
    else             { src = Wout; off = OFF_WOUT; n = 512 * 512;  }
    int i = blockIdx.x * blockDim.x + threadIdx.x;
    if (i * 4 >= n) return;
    float4 v = ((const float4*)src)[i];
    split4(v, g_w_hi + off + (size_t)i * 4, g_w_lo + off + (size_t)i * 4);
}

// ---------------------------------------------------------------------------
// fused elementwise + bf16 split of hidden_new for out GEMM
// ---------------------------------------------------------------------------
__device__ __forceinline__ float sigf(float x) { return 1.0f / (1.0f + expf(-x)); }

__global__ void fused_cell_kernel(const float* __restrict__ cell_t,
                                  float* __restrict__ dout) {
    int idx = blockIdx.x * blockDim.x + threadIdx.x;   // over BH/4
    const int nb4 = BH / 4;
    if (idx >= nb4) return;

    const float4* c4  = (const float4*)cell_t;
    float4* hid = (float4*)(dout + (size_t)BB * OUTN);
    float4* hc  = (float4*)(dout + (size_t)2 * BB * OUTN);
    float4* dv  = (float4*)(dout + (size_t)2 * BB * OUTN + (size_t)KFR * BH);

    float4 zf = ((const float4*)g_z[3])[idx];
    float4 d;
    d.x = 0.5f * sigf(zf.x); d.y = 0.5f * sigf(zf.y);
    d.z = 0.5f * sigf(zf.z); d.w = 0.5f * sigf(zf.w);
    dv[idx] = d;

    float4 w   = make_float4(1.f, 1.f, 1.f, 1.f);
    float4 acc = make_float4(0.f, 0.f, 0.f, 0.f);
#pragma unroll
    for (int j = KFR - 1; j >= 0; j--) {
        float fi  = (float)(KFR - 1 - j);
        float inv = 1.0f / (float)(KFR - j);
        w.x *= (fi - d.x) * inv;  w.y *= (fi - d.y) * inv;
        w.z *= (fi - d.z) * inv;  w.w *= (fi - d.w) * inv;
        float4 cv = c4[(size_t)j * nb4 + idx];
        acc.x = fmaf(w.x, cv.x, acc.x);  acc.y = fmaf(w.y, cv.y, acc.y);
        acc.z = fmaf(w.z, cv.z, acc.z);  acc.w = fmaf(w.w, cv.w, acc.w);
        if (j >= 1) hc[(size_t)(j - 1) * nb4 + idx] = cv;
    }

    float4 zi = ((const float4*)g_z[0])[idx];
    float4 zo = ((const float4*)g_z[1])[idx];
    float4 zc = ((const float4*)g_z[2])[idx];

    float4 cell;
    cell.x = -acc.x + tanhf(zc.x) * sigf(zi.x);
    cell.y = -acc.y + tanhf(zc.y) * sigf(zi.y);
    cell.z = -acc.z + tanhf(zc.z) * sigf(zi.z);
    cell.w = -acc.w + tanhf(zc.w) * sigf(zi.w);
    hc[(size_t)(KFR - 1) * nb4 + idx] = cell;

    float4 hn;
    hn.x = tanhf(cell.x) * sigf(zo.x);
    hn.y = tanhf(cell.y) * sigf(zo.y);
    hn.z = tanhf(cell.z) * sigf(zo.z);
    hn.w = tanhf(cell.w) * sigf(zo.w);
    hid[idx] = hn;

    split4(hn, g_hid_hi + idx * 4, g_hid_lo + idx * 4);
}

// ---------------------------------------------------------------------------
extern "C" void kernel_launch(void* const* d_in, const int* in_sizes, int n_in,
                              void* d_out_v, int out_size) {
    const float* sample = (const float*)d_in[0];
    const float* hidden = (const float*)d_in[1];
    const float* cell_t = (const float*)d_in[2];
    const float* d0     = (const float*)d_in[3];
    const float* Wc     = (const float*)d_in[4];
    const float* bc     = (const float*)d_in[5];
    const float* Wi     = (const float*)d_in[6];
    const float* bi     = (const float*)d_in[7];
    const float* Wf     = (const float*)d_in[8];
    const float* bf     = (const float*)d_in[9];
    const float* Wo     = (const float*)d_in[10];
    const float* bo     = (const float*)d_in[11];
    const float* Wout   = (const float*)d_in[12];
    const float* bout   = (const float*)d_in[13];
    float* out = (float*)d_out_v;

    cudaFuncSetAttribute(gates_mma_kernel,
                         cudaFuncAttributeMaxDynamicSharedMemorySize, SMEM_TOT);
    cudaFuncSetAttribute(out_mma_kernel,
                         cudaFuncAttributeMaxDynamicSharedMemorySize, SMEM_TOT);

    // 1) build bf16 hi/lo of combined_d and all weights
    comb_conv_kernel<<<(BB * KD / 4 + 255) / 256, 256>>>(sample, hidden, d0);
    dim3 wgrid((512 * 1536 / 4 + 255) / 256, 5);
    w_conv_kernel<<<wgrid, 256>>>(Wi, Wo, Wc, Wf, Wout);

    // 2) 4 gate GEMMs via mma.sync (split-bf16, fp32 accum)
    dim3 ggrid(HH / 128, BB / 128, 4);
    gates_mma_kernel<<<ggrid, 256, SMEM_TOT>>>(bi, bo, bc, bf);

    // 3) fused elementwise + hidden_new bf16 split
    fused_cell_kernel<<<(BH / 4 + 255) / 256, 256>>>(cell_t, out);

    // 4) output GEMM via mma.sync
    dim3 ogrid(OUTN / 128, BB / 128, 1);
    out_mma_kernel<<<ogrid, 256, SMEM_TOT>>>(bout, out);
}

// round 4
// speedup vs baseline: 2.5925x; 1.0002x over previous
#include <cuda_runtime.h>
#include <cuda_bf16.h>
#include <math.h>
#include <stdint.h>

#define BB   2048
#define INN  512
#define HH   512
#define KFR  32
#define OUTN 512
#define KD   1536            // IN + 2H (combined_d width)
#define KC   1024            // IN + H
#define BH   (BB*HH)

#define OFF_WI   0
#define OFF_WO   (512*1024)
#define OFF_WC   (2*512*1024)
#define OFF_WF   (3*512*1024)
#define OFF_WOUT (3*512*1024 + 512*1536)
#define W_TOTAL  (OFF_WOUT + 512*512)

#define TILE_B   16384       // one 128x64 bf16 tile in smem
#define STAGE_B  (4*TILE_B)  // Ahi, Alo, Bhi, Blo
#define NSTAGE   3
#define SMEM_TOT (NSTAGE*STAGE_B)   // 196608

// ---------------- static device scratch ----------------
__device__ __nv_bfloat16 g_comb_hi[BB*KD];
__device__ __nv_bfloat16 g_comb_lo[BB*KD];
__device__ __nv_bfloat16 g_w_hi[W_TOTAL];
__device__ __nv_bfloat16 g_w_lo[W_TOTAL];
__device__ __nv_bfloat16 g_hid_hi[BH];
__device__ __nv_bfloat16 g_hid_lo[BH];
__device__ float g_z[4][BH];          // pre-activations: 0=i, 1=o, 2=c, 3=f

// ---------------- PTX helpers (baseline ISA only) ----------------
__device__ __forceinline__ uint32_t smem_u32(const void* p) {
    return (uint32_t)__cvta_generic_to_shared(p);
}

__device__ __forceinline__ void cp16(uint32_t daddr, const void* g) {
    asm volatile("cp.async.cg.shared.global [%0], [%1], 16;" :: "r"(daddr), "l"(g) : "memory");
}
#define CP_COMMIT() asm volatile("cp.async.commit_group;" ::: "memory")
template <int N>
__device__ __forceinline__ void cp_wait() {
    asm volatile("cp.async.wait_group %0;" :: "n"(N) : "memory");
}

__device__ __forceinline__ void ldsm4(uint32_t addr, uint32_t* r) {
    asm volatile("ldmatrix.sync.aligned.m8n8.x4.shared.b16 {%0,%1,%2,%3}, [%4];"
        : "=r"(r[0]), "=r"(r[1]), "=r"(r[2]), "=r"(r[3]) : "r"(addr));
}

__device__ __forceinline__ void mma_bf16(float* c, const uint32_t* a, const uint32_t* b) {
    asm volatile("mma.sync.aligned.m16n8k16.row.col.f32.bf16.bf16.f32 "
        "{%0,%1,%2,%3}, {%4,%5,%6,%7}, {%8,%9}, {%0,%1,%2,%3};"
        : "+f"(c[0]), "+f"(c[1]), "+f"(c[2]), "+f"(c[3])
        : "r"(a[0]), "r"(a[1]), "r"(a[2]), "r"(a[3]), "r"(b[0]), "r"(b[1]));
}

// ---------------------------------------------------------------------------
// cp.async loader: one K-chunk (64 cols) of the 4 tiles into one stage.
// 256 threads; per tile 128 rows x 8 x 16B chunks = 1024 cp16 -> 4 per thread.
// swizzle: phys_col16 = col16 ^ (row & 7)
// ---------------------------------------------------------------------------
__device__ __forceinline__ void load_stage(uint32_t sbase,
    const char* a_hi, const char* a_lo, const char* b_hi, const char* b_lo,
    int lda_b, int ldb_b, int k0b, int tid) {
    const char* srcs[4] = {a_hi, a_lo, b_hi, b_lo};
    const int lds[4] = {lda_b, lda_b, ldb_b, ldb_b};
#pragma unroll
    for (int t = 0; t < 4; t++) {
#pragma unroll
        for (int i = 0; i < 4; i++) {
            int idx = i * 256 + tid;
            int row = idx >> 3;
            uint32_t ch = (uint32_t)(idx & 7) * 16;
            uint32_t off = (uint32_t)row * 128 + (ch ^ (((uint32_t)row & 7) << 4));
            cp16(sbase + t * TILE_B + off,
                 srcs[t] + (size_t)row * lds[t] + k0b + ch);
        }
    }
}

// ---------------------------------------------------------------------------
// split-bf16 mma.sync GEMM tile: C[m,n] = sum_k A[m,k]*B[n,k] + bias[n]
// 128x128 tile, 8 warps (4x2), warp tile 32x64, 3-stage cp.async pipeline.
// ---------------------------------------------------------------------------
__device__ __forceinline__ void mma_gemm_tile(
    const __nv_bfloat16* Ahi, const __nv_bfloat16* Alo, int lda,
    const __nv_bfloat16* Bhi, const __nv_bfloat16* Blo, int ldb,
    const float* __restrict__ bias, float* __restrict__ C, int ldc,
    int K, int blockM, int blockN) {
    extern __shared__ __align__(1024) char dsm[];
    const int tid  = threadIdx.x;
    const int lane = tid & 31;
    const int wid  = tid >> 5;
    const int wm   = wid & 3;    // 0..3 -> 32-row slab
    const int wn   = wid >> 2;   // 0..1 -> 64-col slab
    uint32_t sb = smem_u32(dsm);

    const uint32_t a_kb = ((uint32_t)lane >> 4) * 16;          // 0/16
    const uint32_t b_kb = (((uint32_t)lane >> 3) & 1) * 16;    // 0/16
    uint32_t aRow[2], aXor[2];
#pragma unroll
    for (int mt = 0; mt < 2; mt++) {
        int r = wm * 32 + mt * 16 + (lane & 15);
        aRow[mt] = (uint32_t)r * 128;
        aXor[mt] = ((uint32_t)r & 7) << 4;
    }
    uint32_t bRow[4], bXor[4];
#pragma unroll
    for (int g = 0; g < 4; g++) {
        int r = wn * 64 + g * 16 + (((lane >> 4) << 3) + (lane & 7));
        bRow[g] = (uint32_t)r * 128;
        bXor[g] = ((uint32_t)r & 7) << 4;
    }

    float acc[2][8][4];
#pragma unroll
    for (int mt = 0; mt < 2; mt++)
#pragma unroll
        for (int nt = 0; nt < 8; nt++)
#pragma unroll
            for (int j = 0; j < 4; j++) acc[mt][nt][j] = 0.0f;

    const char* aH = (const char*)(Ahi + (size_t)blockM * lda);
    const char* aL = (const char*)(Alo + (size_t)blockM * lda);
    const char* bH = (const char*)(Bhi + (size_t)blockN * ldb);
    const char* bL = (const char*)(Blo + (size_t)blockN * ldb);
    const int lda_b = lda * 2, ldb_b = ldb * 2;
    const int NC = K / 64;

    // prologue: stages 0 and 1 in flight
    load_stage(sb, aH, aL, bH, bL, lda_b, ldb_b, 0, tid);
    CP_COMMIT();
    load_stage(sb + STAGE_B, aH, aL, bH, bL, lda_b, ldb_b, 128, tid);
    CP_COMMIT();

    int stage = 0;
    for (int c = 0; c < NC; ++c) {
        cp_wait<1>();          // chunk c resident (c+1 may still be in flight)
        __syncthreads();       // all warps done reading the stage about to be refilled
        if (c + 2 < NC) {
            int s2 = stage + 2; if (s2 >= NSTAGE) s2 -= NSTAGE;
            load_stage(sb + (uint32_t)s2 * STAGE_B, aH, aL, bH, bL,
                       lda_b, ldb_b, (c + 2) * 128, tid);
        }
        CP_COMMIT();           // uniform group accounting (may be empty)

        const uint32_t st = sb + (uint32_t)stage * STAGE_B;
#pragma unroll
        for (int kk = 0; kk < 4; kk++) {
            uint32_t ah[2][4], al[2][4];
#pragma unroll
            for (int mt = 0; mt < 2; mt++) {
                uint32_t col = ((uint32_t)(kk * 32) + a_kb) ^ aXor[mt];
                ldsm4(st + 0 * TILE_B + aRow[mt] + col, ah[mt]);
                ldsm4(st + 1 * TILE_B + aRow[mt] + col, al[mt]);
            }
            uint32_t bh[8][2], bl[8][2];
#pragma unroll
            for (int g = 0; g < 4; g++) {
                uint32_t col = ((uint32_t)(kk * 32) + b_kb) ^ bXor[g];
                uint32_t r[4];
                ldsm4(st + 2 * TILE_B + bRow[g] + col, r);
                bh[2*g][0] = r[0]; bh[2*g][1] = r[1];
                bh[2*g+1][0] = r[2]; bh[2*g+1][1] = r[3];
                ldsm4(st + 3 * TILE_B + bRow[g] + col, r);
                bl[2*g][0] = r[0]; bl[2*g][1] = r[1];
                bl[2*g+1][0] = r[2]; bl[2*g+1][1] = r[3];
            }
#pragma unroll
            for (int mt = 0; mt < 2; mt++)
#pragma unroll
                for (int nt = 0; nt < 8; nt++) {
                    mma_bf16(acc[mt][nt], ah[mt], bh[nt]);
                    mma_bf16(acc[mt][nt], ah[mt], bl[nt]);
                    mma_bf16(acc[mt][nt], al[mt], bh[nt]);
                }
        }
        if (++stage >= NSTAGE) stage = 0;
    }

    // epilogue: add bias, store fp32
#pragma unroll
    for (int mt = 0; mt < 2; mt++) {
        int r0 = blockM + wm * 32 + mt * 16 + (lane >> 2);
#pragma unroll
        for (int nt = 0; nt < 8; nt++) {
            int col = blockN + wn * 64 + nt * 8 + (lane & 3) * 2;
            float b0 = bias[col], b1 = bias[col + 1];
            float2 v0 = {acc[mt][nt][0] + b0, acc[mt][nt][1] + b1};
            float2 v1 = {acc[mt][nt][2] + b0, acc[mt][nt][3] + b1};
            *(float2*)(C + (size_t)r0 * ldc + col) = v0;
            *(float2*)(C + (size_t)(r0 + 8) * ldc + col) = v1;
        }
    }
}

// ---------------------------------------------------------------------------
// z order: 0 = Wf (K=1536, longest -> first wave), then i, o, c
__global__ __launch_bounds__(256, 1)
void gates_mma_kernel(const float* __restrict__ bi, const float* __restrict__ bo,
                      const float* __restrict__ bc, const float* __restrict__ bf) {
    int z = blockIdx.z;
    const __nv_bfloat16 *wh, *wl; const float* bias; int K; float* dst;
    if      (z == 0) { wh = g_w_hi + OFF_WF; wl = g_w_lo + OFF_WF; bias = bf; K = KD; dst = g_z[3]; }
    else if (z == 1) { wh = g_w_hi + OFF_WI; wl = g_w_lo + OFF_WI; bias = bi; K = KC; dst = g_z[0]; }
    else if (z == 2) { wh = g_w_hi + OFF_WO; wl = g_w_lo + OFF_WO; bias = bo; K = KC; dst = g_z[1]; }
    else             { wh = g_w_hi + OFF_WC; wl = g_w_lo + OFF_WC; bias = bc; K = KC; dst = g_z[2]; }
    mma_gemm_tile(g_comb_hi, g_comb_lo, KD, wh, wl, K, bias, dst, HH, K,
                  blockIdx.y * 128, blockIdx.x * 128);
}

__global__ __launch_bounds__(256, 1)
void out_mma_kernel(const float* __restrict__ bout, float* __restrict__ out) {
    mma_gemm_tile(g_hid_hi, g_hid_lo, HH,
                  g_w_hi + OFF_WOUT, g_w_lo + OFF_WOUT, HH,
                  bout, out, OUTN, HH, blockIdx.y * 128, blockIdx.x * 128);
}

// ---------------------------------------------------------------------------
// conversions: fp32 -> bf16 hi/lo split
// ---------------------------------------------------------------------------
__device__ __forceinline__ void split4(float4 v, __nv_bfloat16* hi, __nv_bfloat16* lo) {
    float f[4] = {v.x, v.y, v.z, v.w};
    union { __nv_bfloat16 h[4]; uint2 u; } H, L;
#pragma unroll
    for (int i = 0; i < 4; i++) {
        __nv_bfloat16 h = __float2bfloat16_rn(f[i]);
        H.h[i] = h;
        L.h[i] = __float2bfloat16_rn(f[i] - __bfloat162float(h));
    }
    *(uint2*)hi = H.u;
    *(uint2*)lo = L.u;
}

__global__ void comb_conv_kernel(const float* __restrict__ sample,
                                 const float* __restrict__ hidden,
                                 const float* __restrict__ d0) {
    int idx = blockIdx.x * blockDim.x + threadIdx.x;   // over BB*KD/4
    if (idx >= BB * KD / 4) return;
    int b  = idx / (KD / 4);
    int c4 = idx % (KD / 4);
    float4 v;
    if (c4 < INN / 4)            v = ((const float4*)sample)[b * (INN/4) + c4];
    else if (c4 < (INN+HH) / 4)  v = ((const float4*)hidden)[b * (HH/4) + (c4 - INN/4)];
    else                         v = ((const float4*)d0)[b * (HH/4) + (c4 - (INN+HH)/4)];
    split4(v, g_comb_hi + idx * 4, g_comb_lo + idx * 4);
}

__global__ void w_conv_kernel(const float* __restrict__ Wi, const float* __restrict__ Wo,
                              const float* __restrict__ Wc, const float* __restrict__ Wf,
                              const float* __restrict__ Wout) {
    int a = blockIdx.y;
    const float* src; size_t off; int n;
    if      (a == 0) { src = Wi;   off = OFF_WI;   n = 512 * 1024; }
    else if (a == 1) { src = Wo;   off = OFF_WO;   n = 512 * 1024; }
    else if (a == 2) { src = Wc;   off = OFF_WC;   n = 512 * 1024; }
    else if (a == 3) { src = Wf;   off = OFF_WF;   n = 512 * 1536; }
    else             { src = Wout; off = OFF_WOUT; n = 512 * 512;  }
    int i = blockIdx.x * blockDim.x + threadIdx.x;
    if (i * 4 >= n) return;
    float4 v = ((const float4*)src)[i];
    split4(v, g_w_hi + off + (size_t)i * 4, g_w_lo + off + (size_t)i * 4);
}

// ---------------------------------------------------------------------------
// fused elementwise + bf16 split of hidden_new; next-slice prefetch for MLP
// ---------------------------------------------------------------------------
__device__ __forceinline__ float sigf(float x) { return 1.0f / (1.0f + expf(-x)); }

__global__ void fused_cell_kernel(const float* __restrict__ cell_t,
                                  float* __restrict__ dout) {
    int idx = blockIdx.x * blockDim.x + threadIdx.x;   // over BH/4
    const int nb4 = BH / 4;
    if (idx >= nb4) return;

    const float4* c4  = (const float4*)cell_t;
    float4* hid = (float4*)(dout + (size_t)BB * OUTN);
    float4* hc  = (float4*)(dout + (size_t)2 * BB * OUTN);
    float4* dv  = (float4*)(dout + (size_t)2 * BB * OUTN + (size_t)KFR * BH);

    float4 zf = ((const float4*)g_z[3])[idx];
    float4 d;
    d.x = 0.5f * sigf(zf.x); d.y = 0.5f * sigf(zf.y);
    d.z = 0.5f * sigf(zf.z); d.w = 0.5f * sigf(zf.w);
    dv[idx] = d;

    float4 w   = make_float4(1.f, 1.f, 1.f, 1.f);
    float4 acc = make_float4(0.f, 0.f, 0.f, 0.f);
    float4 cv  = c4[(size_t)(KFR - 1) * nb4 + idx];
#pragma unroll
    for (int j = KFR - 1; j >= 0; j--) {
        float4 nxt;
        if (j >= 1) nxt = c4[(size_t)(j - 1) * nb4 + idx];   // prefetch next slice
        float fi  = (float)(KFR - 1 - j);
        float inv = 1.0f / (float)(KFR - j);
        w.x *= (fi - d.x) * inv;  w.y *= (fi - d.y) * inv;
        w.z *= (fi - d.z) * inv;  w.w *= (fi - d.w) * inv;
        acc.x = fmaf(w.x, cv.x, acc.x);  acc.y = fmaf(w.y, cv.y, acc.y);
        acc.z = fmaf(w.z, cv.z, acc.z);  acc.w = fmaf(w.w, cv.w, acc.w);
        if (j >= 1) { hc[(size_t)(j - 1) * nb4 + idx] = cv; cv = nxt; }
    }

    float4 zi = ((const float4*)g_z[0])[idx];
    float4 zo = ((const float4*)g_z[1])[idx];
    float4 zc = ((const float4*)g_z[2])[idx];

    float4 cell;
    cell.x = -acc.x + tanhf(zc.x) * sigf(zi.x);
    cell.y = -acc.y + tanhf(zc.y) * sigf(zi.y);
    cell.z = -acc.z + tanhf(zc.z) * sigf(zi.z);
    cell.w = -acc.w + tanhf(zc.w) * sigf(zi.w);
    hc[(size_t)(KFR - 1) * nb4 + idx] = cell;

    float4 hn;
    hn.x = tanhf(cell.x) * sigf(zo.x);
    hn.y = tanhf(cell.y) * sigf(zo.y);
    hn.z = tanhf(cell.z) * sigf(zo.z);
    hn.w = tanhf(cell.w) * sigf(zo.w);
    hid[idx] = hn;

    split4(hn, g_hid_hi + idx * 4, g_hid_lo + idx * 4);
}

// ---------------------------------------------------------------------------
extern "C" void kernel_launch(void* const* d_in, const int* in_sizes, int n_in,
                              void* d_out_v, int out_size) {
    const float* sample = (const float*)d_in[0];
    const float* hidden = (const float*)d_in[1];
    const float* cell_t = (const float*)d_in[2];
    const float* d0     = (const float*)d_in[3];
    const float* Wc     = (const float*)d_in[4];
    const float* bc     = (const float*)d_in[5];
    const float* Wi     = (const float*)d_in[6];
    const float* bi     = (const float*)d_in[7];
    const float* Wf     = (const float*)d_in[8];
    const float* bf     = (const float*)d_in[9];
    const float* Wo     = (const float*)d_in[10];
    const float* bo     = (const float*)d_in[11];
    const float* Wout   = (const float*)d_in[12];
    const float* bout   = (const float*)d_in[13];
    float* out = (float*)d_out_v;

    cudaFuncSetAttribute(gates_mma_kernel,
                         cudaFuncAttributeMaxDynamicSharedMemorySize, SMEM_TOT);
    cudaFuncSetAttribute(out_mma_kernel,
                         cudaFuncAttributeMaxDynamicSharedMemorySize, SMEM_TOT);

    // 1) build bf16 hi/lo of combined_d and all weights
    comb_conv_kernel<<<(BB * KD / 4 + 255) / 256, 256>>>(sample, hidden, d0);
    dim3 wgrid((512 * 1536 / 4 + 255) / 256, 5);
    w_conv_kernel<<<wgrid, 256>>>(Wi, Wo, Wc, Wf, Wout);

    // 2) 4 gate GEMMs via mma.sync (split-bf16, fp32 accum), Wf first
    dim3 ggrid(HH / 128, BB / 128, 4);
    gates_mma_kernel<<<ggrid, 256, SMEM_TOT>>>(bi, bo, bc, bf);

    // 3) fused elementwise + hidden_new bf16 split
    fused_cell_kernel<<<(BH / 4 + 255) / 256, 256>>>(cell_t, out);

    // 4) output GEMM via mma.sync
    dim3 ogrid(OUTN / 128, BB / 128, 1);
    out_mma_kernel<<<ogrid, 256, SMEM_TOT>>>(bout, out);
}